// round 8
// baseline (speedup 1.0000x reference)
#include <cuda_runtime.h>
#include <cuda_bf16.h>
#include <cstdint>

#define BB 4
#define SS 1024
#define DD 1024
#define HH 16
#define DH 64
#define MTOT (BB * SS)          // 4096

// ================= scratch (static device memory; no allocs) =================
__device__ __nv_bfloat16 g_q_hi[MTOT * DD], g_q_lo[MTOT * DD];
__device__ __nv_bfloat16 g_k_hi[MTOT * DD], g_k_lo[MTOT * DD];
__device__ __nv_bfloat16 g_v_hi[MTOT * DD], g_v_lo[MTOT * DD];
__device__ __nv_bfloat16 g_wq_hi[DD * DD], g_wq_lo[DD * DD];   // W^T [n][k]
__device__ __nv_bfloat16 g_wk_hi[DD * DD], g_wk_lo[DD * DD];
__device__ __nv_bfloat16 g_wv_hi[DD * DD], g_wv_lo[DD * DD];
__device__ __nv_bfloat16 g_wo_hi[DD * DD], g_wo_lo[DD * DD];
// projected heads
__device__ __nv_bfloat16 g_qph[BB * HH * SS * DH], g_qpl[BB * HH * SS * DH]; // [B,H,S,dh]
__device__ __nv_bfloat16 g_kph[BB * HH * SS * DH], g_kpl[BB * HH * SS * DH];
__device__ __nv_bfloat16 g_vth[BB * HH * DH * SS], g_vtl[BB * HH * DH * SS]; // [B,H,dh,S]
__device__ __nv_bfloat16 g_cx_hi[MTOT * DD], g_cx_lo[MTOT * DD];             // ctx [m][1024]

// ================= helpers =================
static __device__ __forceinline__ uint32_t smem_u32(const void* p) {
    uint32_t a;
    asm("{ .reg .u64 t; cvta.to.shared.u64 t, %1; cvt.u32.u64 %0, t; }"
        : "=r"(a) : "l"(p));
    return a;
}

#define CP_ASYNC16(dst, src) \
    asm volatile("cp.async.cg.shared.global [%0], [%1], 16;" \
                 :: "r"(dst), "l"(src) : "memory")
#define CP_COMMIT()  asm volatile("cp.async.commit_group;" ::: "memory")
#define CP_WAIT(n)   asm volatile("cp.async.wait_group %0;" :: "n"(n) : "memory")

#define LDSM_X4(r, a) \
    asm volatile("ldmatrix.sync.aligned.m8n8.x4.shared.b16 {%0,%1,%2,%3}, [%4];" \
                 : "=r"((r)[0]), "=r"((r)[1]), "=r"((r)[2]), "=r"((r)[3]) : "r"(a))
#define LDSM_X2(r, a) \
    asm volatile("ldmatrix.sync.aligned.m8n8.x2.shared.b16 {%0,%1}, [%2];" \
                 : "=r"((r)[0]), "=r"((r)[1]) : "r"(a))
#define MMA16816(c, a, b) \
    asm volatile("mma.sync.aligned.m16n8k16.row.col.f32.bf16.bf16.f32 " \
                 "{%0,%1,%2,%3}, {%4,%5,%6,%7}, {%8,%9}, {%0,%1,%2,%3};" \
                 : "+f"((c)[0]), "+f"((c)[1]), "+f"((c)[2]), "+f"((c)[3]) \
                 : "r"((a)[0]), "r"((a)[1]), "r"((a)[2]), "r"((a)[3]), \
                   "r"((b)[0]), "r"((b)[1]))

static __device__ __forceinline__ uint32_t pack_bf2(float x, float y) {
    __nv_bfloat16 a = __float2bfloat16(x), b = __float2bfloat16(y);
    uint16_t ua = *(uint16_t*)&a, ub = *(uint16_t*)&b;
    return (uint32_t)ua | ((uint32_t)ub << 16);
}
static __device__ __forceinline__ void split_bf2(float x, float y,
                                                 uint32_t& hi, uint32_t& lo) {
    __nv_bfloat16 hx = __float2bfloat16(x), hy = __float2bfloat16(y);
    float rx = x - __bfloat162float(hx);
    float ry = y - __bfloat162float(hy);
    uint16_t ux = *(uint16_t*)&hx, uy = *(uint16_t*)&hy;
    hi = (uint32_t)ux | ((uint32_t)uy << 16);
    lo = pack_bf2(rx, ry);
}

// ================= conversion kernels =================
__global__ __launch_bounds__(256) void cvt_split_kernel(
    const float* __restrict__ q, const float* __restrict__ k,
    const float* __restrict__ v)
{
    const float* src;
    __nv_bfloat16 *hi, *lo;
    if (blockIdx.y == 0)      { src = q; hi = g_q_hi; lo = g_q_lo; }
    else if (blockIdx.y == 1) { src = k; hi = g_k_hi; lo = g_k_lo; }
    else                      { src = v; hi = g_v_hi; lo = g_v_lo; }

    int i = (blockIdx.x * 256 + threadIdx.x) * 4;
    float4 f = *(const float4*)(src + i);
    __nv_bfloat16 h[4], l[4];
    float val[4] = {f.x, f.y, f.z, f.w};
    #pragma unroll
    for (int j = 0; j < 4; j++) {
        h[j] = __float2bfloat16(val[j]);
        l[j] = __float2bfloat16(val[j] - __bfloat162float(h[j]));
    }
    *(uint2*)(hi + i) = *(uint2*)h;
    *(uint2*)(lo + i) = *(uint2*)l;
}

__global__ __launch_bounds__(256) void cvt_wt_kernel(
    const float* __restrict__ W, __nv_bfloat16* __restrict__ hi,
    __nv_bfloat16* __restrict__ lo, int interleaved)
{
    __shared__ float t[32][33];
    const int tx = threadIdx.x, ty = threadIdx.y;
    const int k0 = blockIdx.x * 32, n0 = blockIdx.y * 32;

    #pragma unroll
    for (int i = 0; i < 4; i++) {
        int k = k0 + ty + i * 8;
        int n = n0 + tx;
        size_t a = interleaved ? ((size_t)(n >> 6) * 65536 + (size_t)k * 64 + (n & 63))
                               : ((size_t)k * 1024 + n);
        t[ty + i * 8][tx] = W[a];
    }
    __syncthreads();
    #pragma unroll
    for (int i = 0; i < 4; i++) {
        int n = n0 + ty + i * 8;
        int k = k0 + tx;
        float v = t[tx][ty + i * 8];
        __nv_bfloat16 h = __float2bfloat16(v);
        hi[(size_t)n * 1024 + k] = h;
        lo[(size_t)n * 1024 + k] = __float2bfloat16(v - __bfloat162float(h));
    }
}

// ================= mma.sync bf16-split GEMM core (256x128 tile, 3-stage) =====
//   CTA tile 256m x 128n, K-chunk 32, 256 threads (8 warps 4m x 2n, 64x64 each)
//   mode 0: out bf16 hi/lo at [B,H,S,dh]
//   mode 2: out bf16 hi/lo at [B,H,dh,S] (transposed)
//   mode 1: out fp32 row-major [m][n]
#define GK 40                            // padded bf16 row stride (80 B)
#define G_AH 0
#define G_AL 20480
#define G_BH 40960
#define G_BL 51200
#define G_STAGE 61440
#define GEMM_SMEM (3 * G_STAGE)          // 184320

static __device__ __forceinline__ void gemm_core(
    const __nv_bfloat16* __restrict__ Ahi, const __nv_bfloat16* __restrict__ Alo,
    const __nv_bfloat16* __restrict__ Bhi, const __nv_bfloat16* __restrict__ Blo,
    const float* __restrict__ bias, float* __restrict__ Cf,
    __nv_bfloat16* __restrict__ Ch, __nv_bfloat16* __restrict__ Cl, int mode,
    char* sm)
{
    const uint32_t smb = smem_u32(sm);
    const int tid    = threadIdx.x;
    const int lane   = tid & 31;
    const int warp   = tid >> 5;
    const int warp_m = warp >> 1;        // 0..3 (64 rows each)
    const int warp_n = warp & 1;         // 0..1 (64 cols each)
    const int m0 = blockIdx.x * 256;
    const int n0 = blockIdx.y * 128;

    const uint32_t aoff = ((warp_m * 64 + (lane & 15)) * GK + ((lane >> 4) * 8)) * 2;
    const uint32_t boff = ((warp_n * 64 + (lane & 7)) * GK + (((lane >> 3) & 1) * 8)) * 2;

    float acc[4][8][4] = {};

    auto issue = [&](int c) {
        const uint32_t sb = smb + (uint32_t)(c % 3) * G_STAGE;
        const int k0 = c * 32;
        #pragma unroll
        for (int j = 0; j < 4; j++) {
            int lin = tid + j * 256;          // 0..1023
            int row = lin >> 2;               // 0..255
            int cg  = lin & 3;
            uint32_t so = (uint32_t)(row * 80 + cg * 16);
            size_t ga = (size_t)(m0 + row) * DD + k0 + cg * 8;
            CP_ASYNC16(sb + G_AH + so, Ahi + ga);
            CP_ASYNC16(sb + G_AL + so, Alo + ga);
        }
        #pragma unroll
        for (int j = 0; j < 2; j++) {
            int lin = tid + j * 256;          // 0..511
            int row = lin >> 2;               // 0..127
            int cg  = lin & 3;
            uint32_t so = (uint32_t)(row * 80 + cg * 16);
            size_t gb = (size_t)(n0 + row) * DD + k0 + cg * 8;
            CP_ASYNC16(sb + G_BH + so, Bhi + gb);
            CP_ASYNC16(sb + G_BL + so, Blo + gb);
        }
    };

    issue(0); CP_COMMIT();
    issue(1); CP_COMMIT();

    for (int c = 0; c < DD / 32; c++) {
        if (c + 2 < DD / 32)      { issue(c + 2); CP_COMMIT(); CP_WAIT(2); }
        else if (c + 1 < DD / 32) { CP_WAIT(1); }
        else                      { CP_WAIT(0); }
        __syncthreads();

        const uint32_t sb = smb + (uint32_t)(c % 3) * G_STAGE;
        #pragma unroll
        for (int kk = 0; kk < 2; kk++) {
            const uint32_t kby = kk * 32;
            uint32_t ah[4][4], al[4][4];
            #pragma unroll
            for (int mf = 0; mf < 4; mf++) {
                uint32_t ra = sb + aoff + (uint32_t)(mf * 16 * 80) + kby;
                LDSM_X4(ah[mf], ra + G_AH);
                LDSM_X4(al[mf], ra + G_AL);
            }
            uint32_t bh[8][2], bl[8][2];
            #pragma unroll
            for (int nf = 0; nf < 8; nf++) {
                uint32_t rb = sb + boff + (uint32_t)(nf * 8 * 80) + kby;
                LDSM_X2(bh[nf], rb + G_BH);
                LDSM_X2(bl[nf], rb + G_BL);
            }
            #pragma unroll
            for (int mf = 0; mf < 4; mf++)
                #pragma unroll
                for (int nf = 0; nf < 8; nf++) {
                    MMA16816(acc[mf][nf], ah[mf], bh[nf]);
                    MMA16816(acc[mf][nf], ah[mf], bl[nf]);
                    MMA16816(acc[mf][nf], al[mf], bh[nf]);
                }
        }
        __syncthreads();
    }

    // ---- epilogue ----
    const int lr = lane >> 2;
    const int lc = (lane & 3) * 2;
    #pragma unroll
    for (int mf = 0; mf < 4; mf++) {
        #pragma unroll
        for (int nf = 0; nf < 8; nf++) {
            int n = n0 + warp_n * 64 + nf * 8 + lc;
            float bv0 = bias[n], bv1 = bias[n + 1];
            #pragma unroll
            for (int half = 0; half < 2; half++) {
                int m = m0 + warp_m * 64 + mf * 16 + lr + half * 8;
                float x = acc[mf][nf][half * 2 + 0] + bv0;
                float y = acc[mf][nf][half * 2 + 1] + bv1;
                if (mode == 1) {
                    *(float2*)(Cf + (size_t)m * DD + n) = make_float2(x, y);
                } else {
                    uint32_t phi, plo;
                    split_bf2(x, y, phi, plo);
                    int bidx = m >> 10, s = m & 1023;
                    int h = n >> 6, e = n & 63;
                    if (mode == 0) {
                        size_t off = (((size_t)bidx * HH + h) * SS + s) * DH + e;
                        *(uint32_t*)(Ch + off) = phi;
                        *(uint32_t*)(Cl + off) = plo;
                    } else {
                        size_t off = (((size_t)bidx * HH + h) * DH + e) * SS + s;
                        Ch[off]      = *(__nv_bfloat16*)&phi;
                        Ch[off + SS] = ((__nv_bfloat16*)&phi)[1];
                        Cl[off]      = *(__nv_bfloat16*)&plo;
                        Cl[off + SS] = ((__nv_bfloat16*)&plo)[1];
                    }
                }
            }
        }
    }
}

__global__ __launch_bounds__(256, 1) void qkv_gemm_kernel(
    const float* __restrict__ bq, const float* __restrict__ bk,
    const float* __restrict__ bv)
{
    extern __shared__ char sm[];
    const int z = blockIdx.z;
    if (z == 0)
        gemm_core(g_q_hi, g_q_lo, g_wq_hi, g_wq_lo, bq, nullptr, g_qph, g_qpl, 0, sm);
    else if (z == 1)
        gemm_core(g_k_hi, g_k_lo, g_wk_hi, g_wk_lo, bk, nullptr, g_kph, g_kpl, 0, sm);
    else
        gemm_core(g_v_hi, g_v_lo, g_wv_hi, g_wv_lo, bv, nullptr, g_vth, g_vtl, 2, sm);
}

__global__ __launch_bounds__(256, 1) void outproj_gemm_kernel(
    const float* __restrict__ bo, float* __restrict__ out)
{
    extern __shared__ char sm[];
    gemm_core(g_cx_hi, g_cx_lo, g_wo_hi, g_wo_lo, bo, out, nullptr, nullptr, 1, sm);
}

// ================= tensor-core fused attention (q=32, cp.async 2-stage) ======
#define ATT_KST 72      // bf16 row stride for q/k (144 B)
#define ATT_VST 136     // bf16 row stride for V^T (272 B)
#define ATT_SCS 1028    // fp32 logits row stride

#define AQ_H 0                            // q hi: 32*144 = 4608
#define AQ_L 4608                         // q lo
#define AK_BASE 9216                      // two K stages of 36864 each
#define AK_STAGE 36864                    // KH 18432 + KL 18432
#define AK_L 18432                        // lo offset within stage
#define AV_L 17408                        // V lo offset within stage (VH 64*272)
#define ARED AK_BASE                      // reduce overlay: 8*32*64*4 = 65536
#define ASC 82944                         // fp32 logits 32*1028*4 = 131584
#define ATT_SMEM (ASC + 32 * ATT_SCS * 4) // 214528

__global__ __launch_bounds__(256, 1) void attn_kernel(float* __restrict__ score_out)
{
    extern __shared__ char sm[];
    const uint32_t smb = smem_u32(sm);
    float* sc = (float*)(sm + ASC);

    const int bh  = blockIdx.y;
    const int q0  = blockIdx.x * 32;
    const int tid = threadIdx.x;
    const int lane = tid & 31;
    const int w    = tid >> 5;

    const __nv_bfloat16* qph = g_qph + (size_t)bh * SS * DH;
    const __nv_bfloat16* qpl = g_qpl + (size_t)bh * SS * DH;
    const __nv_bfloat16* kph = g_kph + (size_t)bh * SS * DH;
    const __nv_bfloat16* kpl = g_kpl + (size_t)bh * SS * DH;
    const __nv_bfloat16* vth = g_vth + (size_t)bh * DH * SS;
    const __nv_bfloat16* vtl = g_vtl + (size_t)bh * DH * SS;

    // ---- load q tile (32 x 64) hi/lo ----
    {
        int row = tid >> 3, grp = tid & 7;
        size_t src = (size_t)(q0 + row) * DH + grp * 8;
        uint32_t dst = (uint32_t)(row * 144 + grp * 16);
        *(uint4*)(sm + AQ_H + dst) = *(const uint4*)(qph + src);
        *(uint4*)(sm + AQ_L + dst) = *(const uint4*)(qpl + src);
    }

    const uint32_t a_off = ((lane & 15) * ATT_KST + (lane >> 4) * 8) * 2;
    const uint32_t b_off = (((lane & 7)) * ATT_KST + ((lane >> 3) & 1) * 8) * 2;
    const uint32_t bv_off = (((lane & 7)) * ATT_VST + ((lane >> 3) & 1) * 8) * 2;

    // ---- phase 1: logits (cp.async double-buffered K chunks) ----
    {
        auto issueK = [&](int c) {
            const uint32_t sb = smb + AK_BASE + (c & 1) * AK_STAGE;
            const int c0 = c * 128;
            #pragma unroll
            for (int i = 0; i < 4; i++) {
                int lin = tid + i * 256;
                int row = lin >> 3, grp = lin & 7;
                size_t src = (size_t)(c0 + row) * DH + grp * 8;
                uint32_t dst = sb + (uint32_t)(row * 144 + grp * 16);
                CP_ASYNC16(dst, kph + src);
                CP_ASYNC16(dst + AK_L, kpl + src);
            }
        };
        issueK(0);
        CP_COMMIT();

        for (int c = 0; c < 8; c++) {
            if (c < 7) { issueK(c + 1); CP_COMMIT(); CP_WAIT(1); }
            else       { CP_WAIT(0); }
            __syncthreads();

            const uint32_t sb = smb + AK_BASE + (c & 1) * AK_STAGE;
            float acc[2][2][4] = {};
            #pragma unroll
            for (int kk = 0; kk < 4; kk++) {
                const uint32_t kby = kk * 32;
                uint32_t ah[2][4], al[2][4];
                #pragma unroll
                for (int mf = 0; mf < 2; mf++) {
                    uint32_t ra = smb + a_off + (uint32_t)(mf * 16 * 144) + kby;
                    LDSM_X4(ah[mf], ra + AQ_H);
                    LDSM_X4(al[mf], ra + AQ_L);
                }
                #pragma unroll
                for (int nf = 0; nf < 2; nf++) {
                    uint32_t rb = sb + b_off
                                + (uint32_t)((w * 16 + nf * 8) * 144) + kby;
                    uint32_t bh[2], bl[2];
                    LDSM_X2(bh, rb);
                    LDSM_X2(bl, rb + AK_L);
                    #pragma unroll
                    for (int mf = 0; mf < 2; mf++) {
                        MMA16816(acc[mf][nf], ah[mf], bh);
                        MMA16816(acc[mf][nf], ah[mf], bl);
                        MMA16816(acc[mf][nf], al[mf], bh);
                    }
                }
            }
            #pragma unroll
            for (int mf = 0; mf < 2; mf++)
                #pragma unroll
                for (int nf = 0; nf < 2; nf++) {
                    int row = mf * 16 + (lane >> 2);
                    int key = c * 128 + w * 16 + nf * 8 + (lane & 3) * 2;
                    *(float2*)&sc[row * ATT_SCS + key] =
                        make_float2(acc[mf][nf][0] * 0.125f, acc[mf][nf][1] * 0.125f);
                    *(float2*)&sc[(row + 8) * ATT_SCS + key] =
                        make_float2(acc[mf][nf][2] * 0.125f, acc[mf][nf][3] * 0.125f);
                }
            __syncthreads();
        }
    }

    // ---- phase 2: exact softmax + score write ----
    {
        for (int rr = 0; rr < 4; rr++) {
            int r = w * 4 + rr;
            float* row = sc + r * ATT_SCS;
            float mx = row[lane];
            #pragma unroll
            for (int i = 1; i < 32; i++) mx = fmaxf(mx, row[i * 32 + lane]);
            #pragma unroll
            for (int o = 16; o; o >>= 1) mx = fmaxf(mx, __shfl_xor_sync(0xFFFFFFFFu, mx, o));

            float sum = 0.f;
            #pragma unroll
            for (int i = 0; i < 32; i++) {
                float e = __expf(row[i * 32 + lane] - mx);
                row[i * 32 + lane] = e;
                sum += e;
            }
            #pragma unroll
            for (int o = 16; o; o >>= 1) sum += __shfl_xor_sync(0xFFFFFFFFu, sum, o);
            float inv = 1.f / sum;

            float* g = score_out + ((size_t)bh * SS + q0 + r) * SS;
            #pragma unroll
            for (int i = 0; i < 32; i++) {
                float p = row[i * 32 + lane] * inv;
                row[i * 32 + lane] = p;
                __stcs(&g[i * 32 + lane], p);
            }
        }
    }
    __syncthreads();

    // ---- phase 3: ctx = P @ V (cp.async double-buffered V chunks) ----
    {
        auto issueV = [&](int c) {
            const uint32_t sb = smb + AK_BASE + (c & 1) * AK_STAGE;
            const int c0 = c * 128;
            #pragma unroll
            for (int i = 0; i < 4; i++) {
                int lin = tid + i * 256;
                int e = lin >> 4, g = lin & 15;
                size_t src = (size_t)e * SS + c0 + g * 8;
                uint32_t dst = sb + (uint32_t)(e * 272 + g * 16);
                CP_ASYNC16(dst, vth + src);
                CP_ASYNC16(dst + AV_L, vtl + src);
            }
        };
        issueV(0);
        CP_COMMIT();

        float acc[2][8][4] = {};
        for (int c = 0; c < 8; c++) {
            if (c < 7) { issueV(c + 1); CP_COMMIT(); CP_WAIT(1); }
            else       { CP_WAIT(0); }
            __syncthreads();

            const uint32_t sb = smb + AK_BASE + (c & 1) * AK_STAGE;
            const int kb = c * 128 + w * 16;   // this warp's 16 keys
            uint32_t pa_h[2][4], pa_l[2][4];
            #pragma unroll
            for (int mf = 0; mf < 2; mf++) {
                int r0 = mf * 16 + (lane >> 2);
                int cc = kb + (lane & 3) * 2;
                float2 p00 = *(float2*)&sc[r0 * ATT_SCS + cc];
                float2 p10 = *(float2*)&sc[(r0 + 8) * ATT_SCS + cc];
                float2 p01 = *(float2*)&sc[r0 * ATT_SCS + cc + 8];
                float2 p11 = *(float2*)&sc[(r0 + 8) * ATT_SCS + cc + 8];
                split_bf2(p00.x, p00.y, pa_h[mf][0], pa_l[mf][0]);
                split_bf2(p10.x, p10.y, pa_h[mf][1], pa_l[mf][1]);
                split_bf2(p01.x, p01.y, pa_h[mf][2], pa_l[mf][2]);
                split_bf2(p11.x, p11.y, pa_h[mf][3], pa_l[mf][3]);
            }
            const uint32_t kwby = (uint32_t)(w * 16 * 2);
            #pragma unroll
            for (int nf = 0; nf < 8; nf++) {
                uint32_t rb = sb + bv_off + (uint32_t)(nf * 8 * 272) + kwby;
                uint32_t bh[2], bl[2];
                LDSM_X2(bh, rb);
                LDSM_X2(bl, rb + AV_L);
                #pragma unroll
                for (int mf = 0; mf < 2; mf++) {
                    MMA16816(acc[mf][nf], pa_h[mf], bh);
                    MMA16816(acc[mf][nf], pa_h[mf], bl);
                    MMA16816(acc[mf][nf], pa_l[mf], bh);
                }
            }
            __syncthreads();
        }

        // cross-warp reduce (8 partials of ctx[32][64])
        float* red = (float*)(sm + ARED);
        #pragma unroll
        for (int mf = 0; mf < 2; mf++)
            #pragma unroll
            for (int nf = 0; nf < 8; nf++) {
                int row = mf * 16 + (lane >> 2);
                int col = nf * 8 + (lane & 3) * 2;
                *(float2*)&red[w * 2048 + row * 64 + col] =
                    make_float2(acc[mf][nf][0], acc[mf][nf][1]);
                *(float2*)&red[w * 2048 + (row + 8) * 64 + col] =
                    make_float2(acc[mf][nf][2], acc[mf][nf][3]);
            }
        __syncthreads();

        {
            const int row = tid >> 3;            // 0..31
            const int cg  = (tid & 7) * 8;       // 0..56
            float o[8];
            #pragma unroll
            for (int j = 0; j < 8; j++) {
                float s = 0.f;
                #pragma unroll
                for (int ww = 0; ww < 8; ww++)
                    s += red[ww * 2048 + row * 64 + cg + j];
                o[j] = s;
            }
            const int b = bh >> 4;
            const int h = bh & 15;
            size_t off = ((size_t)b * SS + q0 + row) * DD + h * DH + cg;
            __align__(16) __nv_bfloat16 hb[8], lb[8];
            #pragma unroll
            for (int j = 0; j < 8; j++) {
                hb[j] = __float2bfloat16(o[j]);
                lb[j] = __float2bfloat16(o[j] - __bfloat162float(hb[j]));
            }
            *(uint4*)(g_cx_hi + off) = *(uint4*)hb;
            *(uint4*)(g_cx_lo + off) = *(uint4*)lb;
        }
    }
}

// ============================================================
extern "C" void kernel_launch(void* const* d_in, const int* in_sizes, int n_in,
                              void* d_out, int out_size)
{
    const float* q  = (const float*)d_in[0];
    const float* k  = (const float*)d_in[1];
    const float* v  = (const float*)d_in[2];
    const float* Wq = (const float*)d_in[3];
    const float* bq = (const float*)d_in[4];
    const float* Wk = (const float*)d_in[5];
    const float* bk = (const float*)d_in[6];
    const float* Wv = (const float*)d_in[7];
    const float* bv = (const float*)d_in[8];
    const float* Wo = (const float*)d_in[9];
    const float* bo = (const float*)d_in[10];

    float* out   = (float*)d_out;
    float* score = out + (size_t)BB * SS * DD;

    cudaFuncSetAttribute(attn_kernel,
                         cudaFuncAttributeMaxDynamicSharedMemorySize, ATT_SMEM);
    cudaFuncSetAttribute(qkv_gemm_kernel,
                         cudaFuncAttributeMaxDynamicSharedMemorySize, GEMM_SMEM);
    cudaFuncSetAttribute(outproj_gemm_kernel,
                         cudaFuncAttributeMaxDynamicSharedMemorySize, GEMM_SMEM);

    __nv_bfloat16 *wqh, *wql, *wkh, *wkl, *wvh, *wvl, *woh, *wol;
    cudaGetSymbolAddress((void**)&wqh, g_wq_hi); cudaGetSymbolAddress((void**)&wql, g_wq_lo);
    cudaGetSymbolAddress((void**)&wkh, g_wk_hi); cudaGetSymbolAddress((void**)&wkl, g_wk_lo);
    cudaGetSymbolAddress((void**)&wvh, g_wv_hi); cudaGetSymbolAddress((void**)&wvl, g_wv_lo);
    cudaGetSymbolAddress((void**)&woh, g_wo_hi); cudaGetSymbolAddress((void**)&wol, g_wo_lo);

    // 1) convert activations + weights to bf16 hi/lo
    {
        dim3 g(MTOT * DD / 1024, 3);
        cvt_split_kernel<<<g, 256>>>(q, k, v);
    }
    {
        dim3 g(32, 32), b(32, 8);
        cvt_wt_kernel<<<g, b>>>(Wq, wqh, wql, 1);
        cvt_wt_kernel<<<g, b>>>(Wk, wkh, wkl, 1);
        cvt_wt_kernel<<<g, b>>>(Wv, wvh, wvl, 1);
        cvt_wt_kernel<<<g, b>>>(Wo, woh, wol, 0);
    }

    // 2) fused QKV projections -> bf16 heads (V transposed)
    {
        dim3 g(MTOT / 256, DD / 128, 3);
        qkv_gemm_kernel<<<g, 256, GEMM_SMEM>>>(bq, bk, bv);
    }

    // 3) tensor-core fused attention
    {
        dim3 g(SS / 32, BB * HH);
        attn_kernel<<<g, 256, ATT_SMEM>>>(score);
    }

    // 4) output projection (fp32 out)
    {
        dim3 g(MTOT / 256, DD / 128);
        outproj_gemm_kernel<<<g, 256, GEMM_SMEM>>>(bo, out);
    }
}

// round 9
// speedup vs baseline: 1.0534x; 1.0534x over previous
#include <cuda_runtime.h>
#include <cuda_bf16.h>
#include <cstdint>

#define BB 4
#define SS 1024
#define DD 1024
#define HH 16
#define DH 64
#define MTOT (BB * SS)          // 4096

// ================= scratch (static device memory; no allocs) =================
__device__ __nv_bfloat16 g_q_hi[MTOT * DD], g_q_lo[MTOT * DD];
__device__ __nv_bfloat16 g_k_hi[MTOT * DD], g_k_lo[MTOT * DD];
__device__ __nv_bfloat16 g_v_hi[MTOT * DD], g_v_lo[MTOT * DD];
__device__ __nv_bfloat16 g_wq_hi[DD * DD], g_wq_lo[DD * DD];   // W^T [n][k]
__device__ __nv_bfloat16 g_wk_hi[DD * DD], g_wk_lo[DD * DD];
__device__ __nv_bfloat16 g_wv_hi[DD * DD], g_wv_lo[DD * DD];
__device__ __nv_bfloat16 g_wo_hi[DD * DD], g_wo_lo[DD * DD];
// projected heads
__device__ __nv_bfloat16 g_qph[BB * HH * SS * DH], g_qpl[BB * HH * SS * DH]; // [B,H,S,dh]
__device__ __nv_bfloat16 g_kph[BB * HH * SS * DH], g_kpl[BB * HH * SS * DH];
__device__ __nv_bfloat16 g_vth[BB * HH * DH * SS], g_vtl[BB * HH * DH * SS]; // [B,H,dh,S]
__device__ __nv_bfloat16 g_cx_hi[MTOT * DD], g_cx_lo[MTOT * DD];             // ctx [m][1024]

// ================= helpers =================
static __device__ __forceinline__ uint32_t smem_u32(const void* p) {
    uint32_t a;
    asm("{ .reg .u64 t; cvta.to.shared.u64 t, %1; cvt.u32.u64 %0, t; }"
        : "=r"(a) : "l"(p));
    return a;
}

#define CP_ASYNC16(dst, src) \
    asm volatile("cp.async.cg.shared.global [%0], [%1], 16;" \
                 :: "r"(dst), "l"(src) : "memory")
#define CP_COMMIT()  asm volatile("cp.async.commit_group;" ::: "memory")
#define CP_WAIT(n)   asm volatile("cp.async.wait_group %0;" :: "n"(n) : "memory")

#define LDSM_X4(r, a) \
    asm volatile("ldmatrix.sync.aligned.m8n8.x4.shared.b16 {%0,%1,%2,%3}, [%4];" \
                 : "=r"((r)[0]), "=r"((r)[1]), "=r"((r)[2]), "=r"((r)[3]) : "r"(a))
#define LDSM_X2(r, a) \
    asm volatile("ldmatrix.sync.aligned.m8n8.x2.shared.b16 {%0,%1}, [%2];" \
                 : "=r"((r)[0]), "=r"((r)[1]) : "r"(a))
#define MMA16816(c, a, b) \
    asm volatile("mma.sync.aligned.m16n8k16.row.col.f32.bf16.bf16.f32 " \
                 "{%0,%1,%2,%3}, {%4,%5,%6,%7}, {%8,%9}, {%0,%1,%2,%3};" \
                 : "+f"((c)[0]), "+f"((c)[1]), "+f"((c)[2]), "+f"((c)[3]) \
                 : "r"((a)[0]), "r"((a)[1]), "r"((a)[2]), "r"((a)[3]), \
                   "r"((b)[0]), "r"((b)[1]))

static __device__ __forceinline__ uint32_t pack_bf2(float x, float y) {
    __nv_bfloat16 a = __float2bfloat16(x), b = __float2bfloat16(y);
    uint16_t ua = *(uint16_t*)&a, ub = *(uint16_t*)&b;
    return (uint32_t)ua | ((uint32_t)ub << 16);
}
static __device__ __forceinline__ void split_bf2(float x, float y,
                                                 uint32_t& hi, uint32_t& lo) {
    __nv_bfloat16 hx = __float2bfloat16(x), hy = __float2bfloat16(y);
    float rx = x - __bfloat162float(hx);
    float ry = y - __bfloat162float(hy);
    uint16_t ux = *(uint16_t*)&hx, uy = *(uint16_t*)&hy;
    hi = (uint32_t)ux | ((uint32_t)uy << 16);
    lo = pack_bf2(rx, ry);
}

// ================= conversion kernels =================
__global__ __launch_bounds__(256) void cvt_split_kernel(
    const float* __restrict__ q, const float* __restrict__ k,
    const float* __restrict__ v)
{
    const float* src;
    __nv_bfloat16 *hi, *lo;
    if (blockIdx.y == 0)      { src = q; hi = g_q_hi; lo = g_q_lo; }
    else if (blockIdx.y == 1) { src = k; hi = g_k_hi; lo = g_k_lo; }
    else                      { src = v; hi = g_v_hi; lo = g_v_lo; }

    int i = (blockIdx.x * 256 + threadIdx.x) * 4;
    float4 f = *(const float4*)(src + i);
    __nv_bfloat16 h[4], l[4];
    float val[4] = {f.x, f.y, f.z, f.w};
    #pragma unroll
    for (int j = 0; j < 4; j++) {
        h[j] = __float2bfloat16(val[j]);
        l[j] = __float2bfloat16(val[j] - __bfloat162float(h[j]));
    }
    *(uint2*)(hi + i) = *(uint2*)h;
    *(uint2*)(lo + i) = *(uint2*)l;
}

// two weights per launch (blockIdx.z selects)
__global__ __launch_bounds__(256) void cvt_wt2_kernel(
    const float* __restrict__ W0, __nv_bfloat16* __restrict__ hi0,
    __nv_bfloat16* __restrict__ lo0, int int0,
    const float* __restrict__ W1, __nv_bfloat16* __restrict__ hi1,
    __nv_bfloat16* __restrict__ lo1, int int1)
{
    const float* W;
    __nv_bfloat16 *hi, *lo;
    int interleaved;
    if (blockIdx.z == 0) { W = W0; hi = hi0; lo = lo0; interleaved = int0; }
    else                 { W = W1; hi = hi1; lo = lo1; interleaved = int1; }

    __shared__ float t[32][33];
    const int tx = threadIdx.x, ty = threadIdx.y;
    const int k0 = blockIdx.x * 32, n0 = blockIdx.y * 32;

    #pragma unroll
    for (int i = 0; i < 4; i++) {
        int k = k0 + ty + i * 8;
        int n = n0 + tx;
        size_t a = interleaved ? ((size_t)(n >> 6) * 65536 + (size_t)k * 64 + (n & 63))
                               : ((size_t)k * 1024 + n);
        t[ty + i * 8][tx] = W[a];
    }
    __syncthreads();
    #pragma unroll
    for (int i = 0; i < 4; i++) {
        int n = n0 + ty + i * 8;
        int k = k0 + tx;
        float v = t[tx][ty + i * 8];
        __nv_bfloat16 h = __float2bfloat16(v);
        hi[(size_t)n * 1024 + k] = h;
        lo[(size_t)n * 1024 + k] = __float2bfloat16(v - __bfloat162float(h));
    }
}

// ================= mma.sync bf16-split GEMM core (R7 config: 128x64, 3 CTA/SM)
#define GK 40
#define G_AH 0
#define G_AL 10240
#define G_BH 20480
#define G_BL 25600
#define G_STAGE 30720
#define GEMM_SMEM (2 * G_STAGE)          // 61440

static __device__ __forceinline__ void gemm_core(
    const __nv_bfloat16* __restrict__ Ahi, const __nv_bfloat16* __restrict__ Alo,
    const __nv_bfloat16* __restrict__ Bhi, const __nv_bfloat16* __restrict__ Blo,
    const float* __restrict__ bias, float* __restrict__ Cf,
    __nv_bfloat16* __restrict__ Ch, __nv_bfloat16* __restrict__ Cl, int mode,
    char* sm)
{
    const uint32_t smb = smem_u32(sm);
    const int tid    = threadIdx.x;
    const int lane   = tid & 31;
    const int warp   = tid >> 5;
    const int warp_m = warp >> 1;
    const int warp_n = warp & 1;
    const int m0 = blockIdx.x * 128;
    const int n0 = blockIdx.y * 64;

    const uint32_t aoff = ((warp_m * 64 + (lane & 15)) * GK + ((lane >> 4) * 8)) * 2;
    const uint32_t boff = ((warp_n * 32 + (lane & 7)) * GK + (((lane >> 3) & 1) * 8)) * 2;

    float acc[4][4][4] = {};

    auto issue = [&](int c) {
        const uint32_t sb = smb + (c & 1) * G_STAGE;
        const int k0 = c * 32;
        #pragma unroll
        for (int j = 0; j < 4; j++) {
            int lin = tid + j * 128;
            int row = lin >> 2;
            int cg  = lin & 3;
            uint32_t so = (uint32_t)(row * 80 + cg * 16);
            size_t ga = (size_t)(m0 + row) * DD + k0 + cg * 8;
            CP_ASYNC16(sb + G_AH + so, Ahi + ga);
            CP_ASYNC16(sb + G_AL + so, Alo + ga);
        }
        #pragma unroll
        for (int j = 0; j < 2; j++) {
            int lin = tid + j * 128;
            int row = lin >> 2;
            int cg  = lin & 3;
            uint32_t so = (uint32_t)(row * 80 + cg * 16);
            size_t gb = (size_t)(n0 + row) * DD + k0 + cg * 8;
            CP_ASYNC16(sb + G_BH + so, Bhi + gb);
            CP_ASYNC16(sb + G_BL + so, Blo + gb);
        }
    };

    issue(0);
    CP_COMMIT();

    for (int c = 0; c < DD / 32; c++) {
        if (c + 1 < DD / 32) {
            issue(c + 1);
            CP_COMMIT();
            CP_WAIT(1);
        } else {
            CP_WAIT(0);
        }
        __syncthreads();

        const uint32_t sb = smb + (c & 1) * G_STAGE;
        #pragma unroll
        for (int kk = 0; kk < 2; kk++) {
            const uint32_t kby = kk * 32;
            uint32_t ah[4][4], al[4][4];
            #pragma unroll
            for (int mf = 0; mf < 4; mf++) {
                uint32_t ra = sb + aoff + (uint32_t)(mf * 16 * 80) + kby;
                LDSM_X4(ah[mf], ra + G_AH);
                LDSM_X4(al[mf], ra + G_AL);
            }
            uint32_t bh[4][2], bl[4][2];
            #pragma unroll
            for (int nf = 0; nf < 4; nf++) {
                uint32_t rb = sb + boff + (uint32_t)(nf * 8 * 80) + kby;
                LDSM_X2(bh[nf], rb + G_BH);
                LDSM_X2(bl[nf], rb + G_BL);
            }
            #pragma unroll
            for (int mf = 0; mf < 4; mf++)
                #pragma unroll
                for (int nf = 0; nf < 4; nf++) {
                    MMA16816(acc[mf][nf], ah[mf], bh[nf]);
                    MMA16816(acc[mf][nf], ah[mf], bl[nf]);
                    MMA16816(acc[mf][nf], al[mf], bh[nf]);
                }
        }
        __syncthreads();
    }

    const int lr = lane >> 2;
    const int lc = (lane & 3) * 2;
    #pragma unroll
    for (int mf = 0; mf < 4; mf++) {
        #pragma unroll
        for (int nf = 0; nf < 4; nf++) {
            int n = n0 + warp_n * 32 + nf * 8 + lc;
            float bv0 = bias[n], bv1 = bias[n + 1];
            #pragma unroll
            for (int half = 0; half < 2; half++) {
                int m = m0 + warp_m * 64 + mf * 16 + lr + half * 8;
                float x = acc[mf][nf][half * 2 + 0] + bv0;
                float y = acc[mf][nf][half * 2 + 1] + bv1;
                if (mode == 1) {
                    *(float2*)(Cf + (size_t)m * DD + n) = make_float2(x, y);
                } else {
                    uint32_t phi, plo;
                    split_bf2(x, y, phi, plo);
                    int bidx = m >> 10, s = m & 1023;
                    int h = n >> 6, e = n & 63;
                    if (mode == 0) {
                        size_t off = (((size_t)bidx * HH + h) * SS + s) * DH + e;
                        *(uint32_t*)(Ch + off) = phi;
                        *(uint32_t*)(Cl + off) = plo;
                    } else {
                        size_t off = (((size_t)bidx * HH + h) * DH + e) * SS + s;
                        Ch[off]      = *(__nv_bfloat16*)&phi;
                        Ch[off + SS] = ((__nv_bfloat16*)&phi)[1];
                        Cl[off]      = *(__nv_bfloat16*)&plo;
                        Cl[off + SS] = ((__nv_bfloat16*)&plo)[1];
                    }
                }
            }
        }
    }
}

__global__ __launch_bounds__(128, 3) void qkv_gemm_kernel(
    const float* __restrict__ bq, const float* __restrict__ bk,
    const float* __restrict__ bv)
{
    extern __shared__ char sm[];
    const int z = blockIdx.z;
    if (z == 0)
        gemm_core(g_q_hi, g_q_lo, g_wq_hi, g_wq_lo, bq, nullptr, g_qph, g_qpl, 0, sm);
    else if (z == 1)
        gemm_core(g_k_hi, g_k_lo, g_wk_hi, g_wk_lo, bk, nullptr, g_kph, g_kpl, 0, sm);
    else
        gemm_core(g_v_hi, g_v_lo, g_wv_hi, g_wv_lo, bv, nullptr, g_vth, g_vtl, 2, sm);
}

__global__ __launch_bounds__(128, 3) void outproj_gemm_kernel(
    const float* __restrict__ bo, float* __restrict__ out)
{
    extern __shared__ char sm[];
    gemm_core(g_cx_hi, g_cx_lo, g_wo_hi, g_wo_lo, bo, out, nullptr, nullptr, 1, sm);
}

// ================= tensor-core fused attention (q=32, cp.async 2-stage) ======
#define ATT_KST 72      // bf16 row stride for q/k (144 B)
#define ATT_VST 136     // bf16 row stride for V^T (272 B)
#define ATT_SCS 1028    // fp32 logits row stride

#define AQ_H 0                            // q hi: 32*144 = 4608
#define AQ_L 4608                         // q lo
#define AK_BASE 9216                      // two K stages of 36864 each
#define AK_STAGE 36864                    // KH 18432 + KL 18432
#define AK_L 18432                        // lo offset within stage
#define AV_L 17408                        // V lo offset within stage (VH 64*272)
#define ARED AK_BASE                      // reduce overlay: 8*32*64*4 = 65536
#define ASC 82944                         // fp32 logits 32*1028*4 = 131584
#define ATT_SMEM (ASC + 32 * ATT_SCS * 4) // 214528

__global__ __launch_bounds__(256, 1) void attn_kernel(float* __restrict__ score_out)
{
    extern __shared__ char sm[];
    const uint32_t smb = smem_u32(sm);
    float* sc = (float*)(sm + ASC);

    const int bh  = blockIdx.y;
    const int q0  = blockIdx.x * 32;
    const int tid = threadIdx.x;
    const int lane = tid & 31;
    const int w    = tid >> 5;

    const __nv_bfloat16* qph = g_qph + (size_t)bh * SS * DH;
    const __nv_bfloat16* qpl = g_qpl + (size_t)bh * SS * DH;
    const __nv_bfloat16* kph = g_kph + (size_t)bh * SS * DH;
    const __nv_bfloat16* kpl = g_kpl + (size_t)bh * SS * DH;
    const __nv_bfloat16* vth = g_vth + (size_t)bh * DH * SS;
    const __nv_bfloat16* vtl = g_vtl + (size_t)bh * DH * SS;

    // ---- load q tile (32 x 64) hi/lo ----
    {
        int row = tid >> 3, grp = tid & 7;
        size_t src = (size_t)(q0 + row) * DH + grp * 8;
        uint32_t dst = (uint32_t)(row * 144 + grp * 16);
        *(uint4*)(sm + AQ_H + dst) = *(const uint4*)(qph + src);
        *(uint4*)(sm + AQ_L + dst) = *(const uint4*)(qpl + src);
    }

    const uint32_t a_off = ((lane & 15) * ATT_KST + (lane >> 4) * 8) * 2;
    const uint32_t b_off = (((lane & 7)) * ATT_KST + ((lane >> 3) & 1) * 8) * 2;
    const uint32_t bv_off = (((lane & 7)) * ATT_VST + ((lane >> 3) & 1) * 8) * 2;

    // V chunk loader (shared by hoisted prefetch + phase 3)
    auto issueV = [&](int c) {
        const uint32_t sb = smb + AK_BASE + (c & 1) * AK_STAGE;
        const int c0 = c * 128;
        #pragma unroll
        for (int i = 0; i < 4; i++) {
            int lin = tid + i * 256;
            int e = lin >> 4, g = lin & 15;
            size_t src = (size_t)e * SS + c0 + g * 8;
            uint32_t dst = sb + (uint32_t)(e * 272 + g * 16);
            CP_ASYNC16(dst, vth + src);
            CP_ASYNC16(dst + AV_L, vtl + src);
        }
    };

    // ---- phase 1: logits (cp.async double-buffered K chunks) ----
    {
        auto issueK = [&](int c) {
            const uint32_t sb = smb + AK_BASE + (c & 1) * AK_STAGE;
            const int c0 = c * 128;
            #pragma unroll
            for (int i = 0; i < 4; i++) {
                int lin = tid + i * 256;
                int row = lin >> 3, grp = lin & 7;
                size_t src = (size_t)(c0 + row) * DH + grp * 8;
                uint32_t dst = sb + (uint32_t)(row * 144 + grp * 16);
                CP_ASYNC16(dst, kph + src);
                CP_ASYNC16(dst + AK_L, kpl + src);
            }
        };
        issueK(0);
        CP_COMMIT();

        for (int c = 0; c < 8; c++) {
            if (c < 7) { issueK(c + 1); CP_COMMIT(); CP_WAIT(1); }
            else       { CP_WAIT(0); }
            __syncthreads();

            const uint32_t sb = smb + AK_BASE + (c & 1) * AK_STAGE;
            float acc[2][2][4] = {};
            #pragma unroll
            for (int kk = 0; kk < 4; kk++) {
                const uint32_t kby = kk * 32;
                uint32_t ah[2][4], al[2][4];
                #pragma unroll
                for (int mf = 0; mf < 2; mf++) {
                    uint32_t ra = smb + a_off + (uint32_t)(mf * 16 * 144) + kby;
                    LDSM_X4(ah[mf], ra + AQ_H);
                    LDSM_X4(al[mf], ra + AQ_L);
                }
                #pragma unroll
                for (int nf = 0; nf < 2; nf++) {
                    uint32_t rb = sb + b_off
                                + (uint32_t)((w * 16 + nf * 8) * 144) + kby;
                    uint32_t bh[2], bl[2];
                    LDSM_X2(bh, rb);
                    LDSM_X2(bl, rb + AK_L);
                    #pragma unroll
                    for (int mf = 0; mf < 2; mf++) {
                        MMA16816(acc[mf][nf], ah[mf], bh);
                        MMA16816(acc[mf][nf], ah[mf], bl);
                        MMA16816(acc[mf][nf], al[mf], bh);
                    }
                }
            }
            #pragma unroll
            for (int mf = 0; mf < 2; mf++)
                #pragma unroll
                for (int nf = 0; nf < 2; nf++) {
                    int row = mf * 16 + (lane >> 2);
                    int key = c * 128 + w * 16 + nf * 8 + (lane & 3) * 2;
                    *(float2*)&sc[row * ATT_SCS + key] =
                        make_float2(acc[mf][nf][0] * 0.125f, acc[mf][nf][1] * 0.125f);
                    *(float2*)&sc[(row + 8) * ATT_SCS + key] =
                        make_float2(acc[mf][nf][2] * 0.125f, acc[mf][nf][3] * 0.125f);
                }
            __syncthreads();
        }
    }

    // ---- hoisted V prefetch: stream first V chunk under softmax ----
    issueV(0);
    CP_COMMIT();

    // ---- phase 2: exact softmax + score write ----
    {
        for (int rr = 0; rr < 4; rr++) {
            int r = w * 4 + rr;
            float* row = sc + r * ATT_SCS;
            float mx = row[lane];
            #pragma unroll
            for (int i = 1; i < 32; i++) mx = fmaxf(mx, row[i * 32 + lane]);
            #pragma unroll
            for (int o = 16; o; o >>= 1) mx = fmaxf(mx, __shfl_xor_sync(0xFFFFFFFFu, mx, o));

            float sum = 0.f;
            #pragma unroll
            for (int i = 0; i < 32; i++) {
                float e = __expf(row[i * 32 + lane] - mx);
                row[i * 32 + lane] = e;
                sum += e;
            }
            #pragma unroll
            for (int o = 16; o; o >>= 1) sum += __shfl_xor_sync(0xFFFFFFFFu, sum, o);
            float inv = 1.f / sum;

            float* g = score_out + ((size_t)bh * SS + q0 + r) * SS;
            #pragma unroll
            for (int i = 0; i < 32; i++) {
                float p = row[i * 32 + lane] * inv;
                row[i * 32 + lane] = p;
                __stcs(&g[i * 32 + lane], p);
            }
        }
    }
    __syncthreads();

    // ---- phase 3: ctx = P @ V (cp.async double-buffered V chunks) ----
    {
        float acc[2][8][4] = {};
        for (int c = 0; c < 8; c++) {
            if (c < 7) { issueV(c + 1); CP_COMMIT(); CP_WAIT(1); }
            else       { CP_WAIT(0); }
            __syncthreads();

            const uint32_t sb = smb + AK_BASE + (c & 1) * AK_STAGE;
            const int kb = c * 128 + w * 16;   // this warp's 16 keys
            uint32_t pa_h[2][4], pa_l[2][4];
            #pragma unroll
            for (int mf = 0; mf < 2; mf++) {
                int r0 = mf * 16 + (lane >> 2);
                int cc = kb + (lane & 3) * 2;
                float2 p00 = *(float2*)&sc[r0 * ATT_SCS + cc];
                float2 p10 = *(float2*)&sc[(r0 + 8) * ATT_SCS + cc];
                float2 p01 = *(float2*)&sc[r0 * ATT_SCS + cc + 8];
                float2 p11 = *(float2*)&sc[(r0 + 8) * ATT_SCS + cc + 8];
                split_bf2(p00.x, p00.y, pa_h[mf][0], pa_l[mf][0]);
                split_bf2(p10.x, p10.y, pa_h[mf][1], pa_l[mf][1]);
                split_bf2(p01.x, p01.y, pa_h[mf][2], pa_l[mf][2]);
                split_bf2(p11.x, p11.y, pa_h[mf][3], pa_l[mf][3]);
            }
            const uint32_t kwby = (uint32_t)(w * 16 * 2);
            #pragma unroll
            for (int nf = 0; nf < 8; nf++) {
                uint32_t rb = sb + bv_off + (uint32_t)(nf * 8 * 272) + kwby;
                uint32_t bh[2], bl[2];
                LDSM_X2(bh, rb);
                LDSM_X2(bl, rb + AV_L);
                #pragma unroll
                for (int mf = 0; mf < 2; mf++) {
                    MMA16816(acc[mf][nf], pa_h[mf], bh);
                    MMA16816(acc[mf][nf], pa_h[mf], bl);
                    MMA16816(acc[mf][nf], pa_l[mf], bh);
                }
            }
            __syncthreads();
        }

        // cross-warp reduce (8 partials of ctx[32][64])
        float* red = (float*)(sm + ARED);
        #pragma unroll
        for (int mf = 0; mf < 2; mf++)
            #pragma unroll
            for (int nf = 0; nf < 8; nf++) {
                int row = mf * 16 + (lane >> 2);
                int col = nf * 8 + (lane & 3) * 2;
                *(float2*)&red[w * 2048 + row * 64 + col] =
                    make_float2(acc[mf][nf][0], acc[mf][nf][1]);
                *(float2*)&red[w * 2048 + (row + 8) * 64 + col] =
                    make_float2(acc[mf][nf][2], acc[mf][nf][3]);
            }
        __syncthreads();

        {
            const int row = tid >> 3;            // 0..31
            const int cg  = (tid & 7) * 8;       // 0..56
            float o[8];
            #pragma unroll
            for (int j = 0; j < 8; j++) {
                float s = 0.f;
                #pragma unroll
                for (int ww = 0; ww < 8; ww++)
                    s += red[ww * 2048 + row * 64 + cg + j];
                o[j] = s;
            }
            const int b = bh >> 4;
            const int h = bh & 15;
            size_t off = ((size_t)b * SS + q0 + row) * DD + h * DH + cg;
            __align__(16) __nv_bfloat16 hb[8], lb[8];
            #pragma unroll
            for (int j = 0; j < 8; j++) {
                hb[j] = __float2bfloat16(o[j]);
                lb[j] = __float2bfloat16(o[j] - __bfloat162float(hb[j]));
            }
            *(uint4*)(g_cx_hi + off) = *(uint4*)hb;
            *(uint4*)(g_cx_lo + off) = *(uint4*)lb;
        }
    }
}

// ============================================================
extern "C" void kernel_launch(void* const* d_in, const int* in_sizes, int n_in,
                              void* d_out, int out_size)
{
    const float* q  = (const float*)d_in[0];
    const float* k  = (const float*)d_in[1];
    const float* v  = (const float*)d_in[2];
    const float* Wq = (const float*)d_in[3];
    const float* bq = (const float*)d_in[4];
    const float* Wk = (const float*)d_in[5];
    const float* bk = (const float*)d_in[6];
    const float* Wv = (const float*)d_in[7];
    const float* bv = (const float*)d_in[8];
    const float* Wo = (const float*)d_in[9];
    const float* bo = (const float*)d_in[10];

    float* out   = (float*)d_out;
    float* score = out + (size_t)BB * SS * DD;

    cudaFuncSetAttribute(attn_kernel,
                         cudaFuncAttributeMaxDynamicSharedMemorySize, ATT_SMEM);
    cudaFuncSetAttribute(qkv_gemm_kernel,
                         cudaFuncAttributeMaxDynamicSharedMemorySize, GEMM_SMEM);
    cudaFuncSetAttribute(outproj_gemm_kernel,
                         cudaFuncAttributeMaxDynamicSharedMemorySize, GEMM_SMEM);

    __nv_bfloat16 *wqh, *wql, *wkh, *wkl, *wvh, *wvl, *woh, *wol;
    cudaGetSymbolAddress((void**)&wqh, g_wq_hi); cudaGetSymbolAddress((void**)&wql, g_wq_lo);
    cudaGetSymbolAddress((void**)&wkh, g_wk_hi); cudaGetSymbolAddress((void**)&wkl, g_wk_lo);
    cudaGetSymbolAddress((void**)&wvh, g_wv_hi); cudaGetSymbolAddress((void**)&wvl, g_wv_lo);
    cudaGetSymbolAddress((void**)&woh, g_wo_hi); cudaGetSymbolAddress((void**)&wol, g_wo_lo);

    // launch 1: activation conversions (fused)
    {
        dim3 g(MTOT * DD / 1024, 3);
        cvt_split_kernel<<<g, 256>>>(q, k, v);
    }
    // launches 2-3: weight conversions (2 weights per launch)
    {
        dim3 g(32, 32, 2), b(32, 8);
        cvt_wt2_kernel<<<g, b>>>(Wq, wqh, wql, 1, Wk, wkh, wkl, 1);
        cvt_wt2_kernel<<<g, b>>>(Wv, wvh, wvl, 1, Wo, woh, wol, 0);
    }
    // launch 4: fused QKV projections
    {
        dim3 g(MTOT / 128, DD / 64, 3);
        qkv_gemm_kernel<<<g, 128, GEMM_SMEM>>>(bq, bk, bv);
    }
    // launch 5: tensor-core fused attention  (ncu captures THIS launch)
    {
        dim3 g(SS / 32, BB * HH);
        attn_kernel<<<g, 256, ATT_SMEM>>>(score);
    }
    // launch 6: output projection
    {
        dim3 g(MTOT / 128, DD / 64);
        outproj_gemm_kernel<<<g, 128, GEMM_SMEM>>>(bo, out);
    }
}